// round 16
// baseline (speedup 1.0000x reference)
#include <cuda_runtime.h>
#include <cuda_fp16.h>

#define NG    20000
#define BATCH 128
#define UNITS 10000
#define DEG   32

// Scratch: |feature| transposed to [gene][batch] in fp16 (5.12 MB, fits L2).
__device__ __align__(256) __half g_featT[(size_t)NG * BATCH];

// ---------------------------------------------------------------------------
// Kernel 1: featT[g][b] = (half)|feature[b][g]|
// r7 structure (conflict-free 32x33 float tile, 128 B coalesced reads) but
// phase 2 now emits ONE uint2 (4 halves) per thread instead of four 2 B
// stores: thread t reads tile[bq..bq+3][gene] (bank = (b+g) mod 32, all 32
// lanes distinct -> conflict-free) and writes 8 B to the gene row.
// Store instructions /4, 64-bit wide, fully-sectored warp stores.
// ---------------------------------------------------------------------------
__global__ __launch_bounds__(256) void transpose_abs_kernel(const float* __restrict__ f) {
    __shared__ float tile[32][33];
    const int g0 = blockIdx.x * 32;      // NG = 625*32, exact
    const int b0 = blockIdx.y * 32;      // BATCH = 4*32, exact
    const int x = threadIdx.x;           // 0..31
    const int y = threadIdx.y;           // 0..7

#pragma unroll
    for (int i = 0; i < 32; i += 8) {
        tile[y + i][x] = fabsf(__ldg(&f[(size_t)(b0 + y + i) * NG + g0 + x]));
    }
    __syncthreads();

    const int t  = y * 32 + x;
    const int gl = t >> 3;               // gene within tile, 0..31
    const int bq = (t & 7) * 4;          // batch quad, 0..28

    float v0 = tile[bq + 0][gl];
    float v1 = tile[bq + 1][gl];
    float v2 = tile[bq + 2][gl];
    float v3 = tile[bq + 3][gl];
    __half2 h0 = __floats2half2_rn(v0, v1);
    __half2 h1 = __floats2half2_rn(v2, v3);
    uint2 o;
    o.x = *(unsigned int*)&h0;
    o.y = *(unsigned int*)&h1;
    *(uint2*)&g_featT[(size_t)(g0 + gl) * BATCH + b0 + bq] = o;
}

// Fast tanh: 1 - 2*rcp(1 + ex2(2*log2e*x)). ~5 instr, ~1e-6 rel err,
// saturates correctly at +/-1.
__device__ __forceinline__ float fast_tanh(float x) {
    float e, r;
    asm("ex2.approx.f32 %0, %1;" : "=f"(e) : "f"(x * 2.88539008177793f));
    float s = 1.0f + e;
    asm("rcp.approx.f32 %0, %1;" : "=f"(r) : "f"(s));
    return fmaf(-2.0f, r, 1.0f);
}

__device__ __forceinline__ __half2 h2(unsigned int v) { return *(__half2*)&v; }

// ---------------------------------------------------------------------------
// Kernel 2: gather + reduce + epilogue.
// r15 structure, pipeline deepened to depth 2: 8 gene-row loads in flight
// (two groups of 4) so LDG latency is covered by TWO reduce windows.
// One warp per unit; lane d holds ppi[u][d]; shfl-broadcast offsets.
// Warp load per gene = 256 B fully coalesced (uint2 per lane).
// ---------------------------------------------------------------------------
__global__ __launch_bounds__(256) void gather_kernel(
    const int*   __restrict__ ppi,
    const float* __restrict__ kern,
    const float* __restrict__ bias,
    float*       __restrict__ out)
{
    __shared__ float so[8 * 129];            // [warp][batch], padded

    const int w    = threadIdx.x >> 5;
    const int lane = threadIdx.x & 31;
    const int u0   = blockIdx.x * 8;         // UNITS = 1250*8
    const int u    = u0 + w;

    // Lane d owns neighbor d; byte offset of its gene row.
    int off = __ldg(&ppi[(size_t)u * DEG + lane]) << 8;

    const char* base = (const char*)g_featT + lane * 8;   // lane's 8 B slice
    float a0 = 0.f, a1 = 0.f, a2 = 0.f, a3 = 0.f;

    uint2 buf[2][4];

    // Prologue: load groups 0 and 1 (genes 0..7) -> 8 LDGs in flight.
#pragma unroll
    for (int p = 0; p < 2; p++) {
        int o0 = __shfl_sync(0xffffffffu, off, p * 4 + 0);
        int o1 = __shfl_sync(0xffffffffu, off, p * 4 + 1);
        int o2 = __shfl_sync(0xffffffffu, off, p * 4 + 2);
        int o3 = __shfl_sync(0xffffffffu, off, p * 4 + 3);
        buf[p][0] = *(const uint2*)(base + o0);
        buf[p][1] = *(const uint2*)(base + o1);
        buf[p][2] = *(const uint2*)(base + o2);
        buf[p][3] = *(const uint2*)(base + o3);
    }

    // Steady state: load group g, reduce group g-2 (4-gene fp16 tree;
    // measured rel_err 2.0e-5 with this tree).
#pragma unroll
    for (int g = 2; g < 8; g++) {
        const int s = g & 1;
        uint2 cA = buf[s][0], cB = buf[s][1], cC = buf[s][2], cD = buf[s][3];

        int o0 = __shfl_sync(0xffffffffu, off, g * 4 + 0);
        int o1 = __shfl_sync(0xffffffffu, off, g * 4 + 1);
        int o2 = __shfl_sync(0xffffffffu, off, g * 4 + 2);
        int o3 = __shfl_sync(0xffffffffu, off, g * 4 + 3);
        buf[s][0] = *(const uint2*)(base + o0);
        buf[s][1] = *(const uint2*)(base + o1);
        buf[s][2] = *(const uint2*)(base + o2);
        buf[s][3] = *(const uint2*)(base + o3);

        __half2 q0 = __hadd2(__hadd2(h2(cA.x), h2(cB.x)), __hadd2(h2(cC.x), h2(cD.x)));
        __half2 q1 = __hadd2(__hadd2(h2(cA.y), h2(cB.y)), __hadd2(h2(cC.y), h2(cD.y)));
        float2 f0 = __half22float2(q0);
        float2 f1 = __half22float2(q1);
        a0 += f0.x; a1 += f0.y; a2 += f1.x; a3 += f1.y;
    }

    // Epilogue: reduce the last two groups (6 and 7) still in the buffer.
#pragma unroll
    for (int p = 0; p < 2; p++) {
        uint2 cA = buf[p][0], cB = buf[p][1], cC = buf[p][2], cD = buf[p][3];
        __half2 q0 = __hadd2(__hadd2(h2(cA.x), h2(cB.x)), __hadd2(h2(cC.x), h2(cD.x)));
        __half2 q1 = __hadd2(__hadd2(h2(cA.y), h2(cB.y)), __hadd2(h2(cC.y), h2(cD.y)));
        float2 f0 = __half22float2(q0);
        float2 f1 = __half22float2(q1);
        a0 += f0.x; a1 += f0.y; a2 += f1.x; a3 += f1.y;
    }

    const float k  = __ldg(&kern[u]);
    const float bi = __ldg(&bias[u]);
    const int   b0 = lane * 4;

    so[w * 129 + b0 + 0] = fast_tanh(fmaf(a0, k, bi));
    so[w * 129 + b0 + 1] = fast_tanh(fmaf(a1, k, bi));
    so[w * 129 + b0 + 2] = fast_tanh(fmaf(a2, k, bi));
    so[w * 129 + b0 + 3] = fast_tanh(fmaf(a3, k, bi));

    __syncthreads();

    // Coalesced writeback: batch rows x 8 consecutive units (32 B runs).
#pragma unroll
    for (int i = threadIdx.x; i < BATCH * 8; i += 256) {
        int b = i >> 3;
        int j = i & 7;
        out[(size_t)b * UNITS + u0 + j] = so[j * 129 + b];
    }
}

// ---------------------------------------------------------------------------
extern "C" void kernel_launch(void* const* d_in, const int* in_sizes, int n_in,
                              void* d_out, int out_size)
{
    (void)in_sizes; (void)n_in; (void)out_size;
    const float* feature = (const float*)d_in[0];
    const int*   ppi     = (const int*)d_in[1];
    const float* kern    = (const float*)d_in[2];
    const float* bias    = (const float*)d_in[3];
    float*       out     = (float*)d_out;

    dim3 tblock(32, 8);
    dim3 tgrid(NG / 32, BATCH / 32);
    transpose_abs_kernel<<<tgrid, tblock>>>(feature);

    gather_kernel<<<UNITS / 8, 256>>>(ppi, kern, bias, out);
}